// round 2
// baseline (speedup 1.0000x reference)
#include <cuda_runtime.h>
#include <cuda_bf16.h>
#include <cstdint>

#define N_NODES 100000
#define N_EDGES 800000
#define D_IN    256      // 64 + 64 + 128
#define D_OUT   128

// Scratch: concatenated x = [agg_a(0:64) | agg_b(64:128) | vdata(128:256)], row-major [N_NODES, 256]
__device__ __align__(16) float g_x[(size_t)N_NODES * D_IN];

// ---------------------------------------------------------------------------
// Kernel 1: init x — zero the aggregation columns, copy vdata into cols 128:256
// One thread per float4 (64 float4 per node row).
// ---------------------------------------------------------------------------
__global__ void init_x_kernel(const float* __restrict__ vdata) {
    int idx = blockIdx.x * blockDim.x + threadIdx.x;
    const int total = N_NODES * 64;           // float4 count
    if (idx >= total) return;
    int node = idx >> 6;
    int q    = idx & 63;
    float4 v;
    if (q < 32) {
        v = make_float4(0.f, 0.f, 0.f, 0.f);
    } else {
        v = reinterpret_cast<const float4*>(vdata)[(size_t)node * 32 + (q - 32)];
    }
    reinterpret_cast<float4*>(g_x)[idx] = v;
}

// ---------------------------------------------------------------------------
// Kernel 2: scatter-add edge features into g_x via vector atomics (REDG.128).
// 16 threads per edge, each handles one float4 of the 64-float row.
// receivers are int32 (JAX silently downcasts int64 -> int32 without x64 mode).
// ---------------------------------------------------------------------------
__global__ void scatter_kernel(const float* __restrict__ edata,
                               const int* __restrict__ recv,
                               int col_off) {
    int idx = blockIdx.x * blockDim.x + threadIdx.x;
    const int total = N_EDGES * 16;
    if (idx >= total) return;
    int edge = idx >> 4;
    int q    = idx & 15;
    float4 v = reinterpret_cast<const float4*>(edata)[(size_t)edge * 16 + q];
    int r = recv[edge];
    float* dst = g_x + (size_t)r * D_IN + col_off + q * 4;
    asm volatile("red.global.add.v4.f32 [%0], {%1, %2, %3, %4};"
                 :: "l"(dst), "f"(v.x), "f"(v.y), "f"(v.z), "f"(v.w)
                 : "memory");
}

// ---------------------------------------------------------------------------
// Kernel 3: GEMM out[100000,128] = x[100000,256] @ W[256,128] + b
// Block: 256 threads, 64-node tile. W (128KB) + x tile (64KB) in dynamic smem.
// Thread tile: 8 nodes x 4 cols. k processed in chunks of 4 (float4 LDS).
// ---------------------------------------------------------------------------
__global__ __launch_bounds__(256, 1)
void gemm_kernel(const float* __restrict__ W,
                 const float* __restrict__ bias,
                 float* __restrict__ out) {
    extern __shared__ float smem[];
    float4* sW4 = reinterpret_cast<float4*>(smem);                // 256x128 floats = 8192 float4
    float4* sX4 = reinterpret_cast<float4*>(smem + D_IN * D_OUT); // 64x256 floats = 4096 float4

    const int tid   = threadIdx.x;
    const int node0 = blockIdx.x * 64;

    // Load W (coalesced, 32 float4 per thread)
    const float4* W4 = reinterpret_cast<const float4*>(W);
    #pragma unroll
    for (int i = 0; i < 32; i++) sW4[i * 256 + tid] = W4[i * 256 + tid];

    // Load x tile (16 float4 per thread), guard partial last tile
    const float4* X4 = reinterpret_cast<const float4*>(g_x);
    #pragma unroll
    for (int i = 0; i < 16; i++) {
        int j = i * 256 + tid;          // float4 idx within tile: node=j>>6, quad=j&63
        int node = node0 + (j >> 6);
        sX4[j] = (node < N_NODES) ? X4[(size_t)node * 64 + (j & 63)]
                                  : make_float4(0.f, 0.f, 0.f, 0.f);
    }
    __syncthreads();

    const int cg = tid & 31;   // col group -> cols cg*4 .. cg*4+3
    const int ng = tid >> 5;   // node group -> nodes ng*8 .. ng*8+7

    float acc[8][4];
    #pragma unroll
    for (int n = 0; n < 8; n++)
        #pragma unroll
        for (int c = 0; c < 4; c++) acc[n][c] = 0.f;

    #pragma unroll 4
    for (int k = 0; k < D_IN; k += 4) {
        float4 wr0 = sW4[(k + 0) * 32 + cg];
        float4 wr1 = sW4[(k + 1) * 32 + cg];
        float4 wr2 = sW4[(k + 2) * 32 + cg];
        float4 wr3 = sW4[(k + 3) * 32 + cg];
        #pragma unroll
        for (int n = 0; n < 8; n++) {
            float4 xv = sX4[(size_t)(ng * 8 + n) * 64 + (k >> 2)];
            acc[n][0] += xv.x * wr0.x + xv.y * wr1.x + xv.z * wr2.x + xv.w * wr3.x;
            acc[n][1] += xv.x * wr0.y + xv.y * wr1.y + xv.z * wr2.y + xv.w * wr3.y;
            acc[n][2] += xv.x * wr0.z + xv.y * wr1.z + xv.z * wr2.z + xv.w * wr3.z;
            acc[n][3] += xv.x * wr0.w + xv.y * wr1.w + xv.z * wr2.w + xv.w * wr3.w;
        }
    }

    float4 b4 = reinterpret_cast<const float4*>(bias)[cg];
    #pragma unroll
    for (int n = 0; n < 8; n++) {
        int node = node0 + ng * 8 + n;
        if (node < N_NODES) {
            float4 o;
            o.x = acc[n][0] + b4.x;
            o.y = acc[n][1] + b4.y;
            o.z = acc[n][2] + b4.z;
            o.w = acc[n][3] + b4.w;
            reinterpret_cast<float4*>(out)[(size_t)node * 32 + cg] = o;
        }
    }
}

// ---------------------------------------------------------------------------
extern "C" void kernel_launch(void* const* d_in, const int* in_sizes, int n_in,
                              void* d_out, int out_size) {
    const float* vdata   = (const float*)d_in[0];
    const float* edata_a = (const float*)d_in[1];
    const float* edata_b = (const float*)d_in[2];
    const int*   conn_a  = (const int*)d_in[3];
    const int*   conn_b  = (const int*)d_in[4];
    const float* W       = (const float*)d_in[5];
    const float* bias    = (const float*)d_in[6];
    float*       out     = (float*)d_out;

    // 1) init concat buffer
    {
        int total = N_NODES * 64;
        int blocks = (total + 255) / 256;
        init_x_kernel<<<blocks, 256>>>(vdata);
    }
    // 2) scatter a and b (receivers = conn[1, :])
    {
        int total = N_EDGES * 16;
        int blocks = (total + 255) / 256;
        scatter_kernel<<<blocks, 256>>>(edata_a, conn_a + N_EDGES, 0);
        scatter_kernel<<<blocks, 256>>>(edata_b, conn_b + N_EDGES, 64);
    }
    // 3) GEMM + bias
    {
        size_t smem_bytes = (size_t)(D_IN * D_OUT + 64 * D_IN) * sizeof(float); // 128KB + 64KB
        cudaFuncSetAttribute(gemm_kernel,
                             cudaFuncAttributeMaxDynamicSharedMemorySize,
                             (int)smem_bytes);
        int blocks = (N_NODES + 63) / 64;
        gemm_kernel<<<blocks, 256, smem_bytes>>>(W, bias, out);
    }
}

// round 4
// speedup vs baseline: 1.2690x; 1.2690x over previous
#include <cuda_runtime.h>
#include <cuda_bf16.h>
#include <cstdint>

#define N_NODES 100000
#define N_EDGES 800000
#define D_IN    256      // 64 + 64 + 128
#define D_OUT   128

#define KPAD    264      // padded k-stride in bf16 elems (132 words) -> bank-conflict-free
#define W_IMG_HALF  67584    // 128 rows * 264 bf16 * 2B
#define W_IMG_TOTAL 135168   // hi + lo

// Scratch: concatenated x = [agg_a(0:64) | agg_b(64:128) | vdata(128:256)]
__device__ __align__(16) float g_x[(size_t)N_NODES * D_IN];

// W^T split images: [n=128][k=264(padded)] bf16, hi at 0, lo at W_IMG_HALF
__device__ __align__(16) unsigned char g_wt[W_IMG_TOTAL];

// ---------------------------------------------------------------------------
// Kernel 0: split W into bf16 hi/lo, transposed into padded image.
// ---------------------------------------------------------------------------
__global__ void prep_w_kernel(const float* __restrict__ W) {
    int idx = blockIdx.x * blockDim.x + threadIdx.x;   // 0 .. 32767
    if (idx >= D_IN * D_OUT) return;
    int n = idx & 127;          // output col  -> B row
    int k = idx >> 7;           // input  dim  -> B col
    float w = W[k * D_OUT + n];
    __nv_bfloat16 h = __float2bfloat16_rn(w);
    __nv_bfloat16 l = __float2bfloat16_rn(w - __bfloat162float(h));
    uint32_t off = (uint32_t)n * (KPAD * 2) + (uint32_t)k * 2;
    *(__nv_bfloat16*)(g_wt + off)              = h;
    *(__nv_bfloat16*)(g_wt + W_IMG_HALF + off) = l;
}

// ---------------------------------------------------------------------------
// Kernel 1: init x — zero agg columns, copy vdata into cols 128:256
// ---------------------------------------------------------------------------
__global__ void init_x_kernel(const float* __restrict__ vdata) {
    int idx = blockIdx.x * blockDim.x + threadIdx.x;
    const int total = N_NODES * 64;
    if (idx >= total) return;
    int node = idx >> 6;
    int q    = idx & 63;
    float4 v;
    if (q < 32) v = make_float4(0.f, 0.f, 0.f, 0.f);
    else        v = reinterpret_cast<const float4*>(vdata)[(size_t)node * 32 + (q - 32)];
    reinterpret_cast<float4*>(g_x)[idx] = v;
}

// ---------------------------------------------------------------------------
// Kernel 2: scatter-add edge features via red.global.add.v4.f32
// ---------------------------------------------------------------------------
__global__ void scatter_kernel(const float* __restrict__ edata,
                               const int* __restrict__ recv,
                               int col_off) {
    int idx = blockIdx.x * blockDim.x + threadIdx.x;
    const int total = N_EDGES * 16;
    if (idx >= total) return;
    int edge = idx >> 4;
    int q    = idx & 15;
    float4 v = reinterpret_cast<const float4*>(edata)[(size_t)edge * 16 + q];
    int r = recv[edge];
    float* dst = g_x + (size_t)r * D_IN + col_off + q * 4;
    asm volatile("red.global.add.v4.f32 [%0], {%1, %2, %3, %4};"
                 :: "l"(dst), "f"(v.x), "f"(v.y), "f"(v.z), "f"(v.w)
                 : "memory");
}

// ---------------------------------------------------------------------------
// mma.sync bf16 helper (baseline PTX, runs on HMMA pipe)
// ---------------------------------------------------------------------------
__device__ __forceinline__ void mma_bf16(float* d, const uint32_t* a,
                                         const uint32_t* b) {
    asm volatile(
        "mma.sync.aligned.m16n8k16.row.col.f32.bf16.bf16.f32 "
        "{%0,%1,%2,%3}, {%4,%5,%6,%7}, {%8,%9}, {%0,%1,%2,%3};"
        : "+f"(d[0]), "+f"(d[1]), "+f"(d[2]), "+f"(d[3])
        : "r"(a[0]), "r"(a[1]), "r"(a[2]), "r"(a[3]),
          "r"(b[0]), "r"(b[1]));
}

// SMEM layout (uint32 words):
//  sWh : [0,        16896)   128 rows x 132 words
//  sWl : [16896,    33792)
//  sXh : [33792,    42240)   64 rows x 132 words
//  sXl : [42240,    50688)
#define SW_H 0
#define SW_L 16896
#define SX_H 33792
#define SX_L 42240
#define SMEM_WORDS 50688     // 202752 bytes

// ---------------------------------------------------------------------------
// Kernel 3: HMMA GEMM, split-bf16: out[100000,128] = x @ W + b
// 256 threads / 8 warps. M_TILE = 64. Warp tile = 16(M) x 64(N).
// ---------------------------------------------------------------------------
__global__ __launch_bounds__(256, 1)
void gemm_mma_kernel(const float* __restrict__ bias, float* __restrict__ out) {
    extern __shared__ uint32_t smem[];
    const int tid  = threadIdx.x;
    const int wid  = tid >> 5;
    const int lane = tid & 31;
    const int grp  = lane >> 2;       // 0..7
    const int qp   = lane & 3;        // 0..3
    const int node0 = blockIdx.x * 64;

    const int m0 = (wid & 3) * 16;    // warp M band within tile
    const int n0 = (wid >> 2) * 64;   // warp N half

    // ---- Stage W^T image (hi+lo, 135168B = 8448 uint4) ----
    {
        const uint4* src = reinterpret_cast<const uint4*>(g_wt);
        uint4* dst = reinterpret_cast<uint4*>(smem);
        #pragma unroll
        for (int i = 0; i < 33; i++) dst[i * 256 + tid] = src[i * 256 + tid];
    }

    // ---- Stage x tile: [64][256] fp32 -> split bf16 hi/lo, padded rows ----
    {
        const float4* X4 = reinterpret_cast<const float4*>(g_x);
        #pragma unroll
        for (int i = 0; i < 16; i++) {
            int j  = i * 256 + tid;     // 0..4095
            int r  = j >> 6;            // tile row 0..63
            int c4 = j & 63;            // float4 idx in row
            int node = node0 + r;
            float4 v = (node < N_NODES)
                     ? X4[(size_t)node * 64 + c4]
                     : make_float4(0.f, 0.f, 0.f, 0.f);
            __nv_bfloat16 h0 = __float2bfloat16_rn(v.x);
            __nv_bfloat16 h1 = __float2bfloat16_rn(v.y);
            __nv_bfloat16 h2 = __float2bfloat16_rn(v.z);
            __nv_bfloat16 h3 = __float2bfloat16_rn(v.w);
            __nv_bfloat16 l0 = __float2bfloat16_rn(v.x - __bfloat162float(h0));
            __nv_bfloat16 l1 = __float2bfloat16_rn(v.y - __bfloat162float(h1));
            __nv_bfloat16 l2 = __float2bfloat16_rn(v.z - __bfloat162float(h2));
            __nv_bfloat16 l3 = __float2bfloat16_rn(v.w - __bfloat162float(h3));
            uint32_t hi01 = ((uint32_t)__bfloat16_as_ushort(h1) << 16) | __bfloat16_as_ushort(h0);
            uint32_t hi23 = ((uint32_t)__bfloat16_as_ushort(h3) << 16) | __bfloat16_as_ushort(h2);
            uint32_t lo01 = ((uint32_t)__bfloat16_as_ushort(l1) << 16) | __bfloat16_as_ushort(l0);
            uint32_t lo23 = ((uint32_t)__bfloat16_as_ushort(l3) << 16) | __bfloat16_as_ushort(l2);
            int wbase = r * 132 + c4 * 2;   // word index within x image
            smem[SX_H + wbase]     = hi01;
            smem[SX_H + wbase + 1] = hi23;
            smem[SX_L + wbase]     = lo01;
            smem[SX_L + wbase + 1] = lo23;
        }
    }
    __syncthreads();

    // ---- Compute: 16 k-steps x 8 n-tiles x 3 split terms ----
    float acc[8][4];
    #pragma unroll
    for (int j = 0; j < 8; j++)
        #pragma unroll
        for (int c = 0; c < 4; c++) acc[j][c] = 0.f;

    #pragma unroll 4
    for (int ks = 0; ks < 16; ks++) {
        uint32_t ah[4], al[4];
        int wA = (m0 + grp) * 132 + ks * 8;
        ah[0] = smem[SX_H + wA + qp];
        ah[1] = smem[SX_H + wA + 1056 + qp];      // +8 rows
        ah[2] = smem[SX_H + wA + 4 + qp];         // +8 k
        ah[3] = smem[SX_H + wA + 1060 + qp];
        al[0] = smem[SX_L + wA + qp];
        al[1] = smem[SX_L + wA + 1056 + qp];
        al[2] = smem[SX_L + wA + 4 + qp];
        al[3] = smem[SX_L + wA + 1060 + qp];

        #pragma unroll
        for (int j = 0; j < 8; j++) {
            int wB = (n0 + j * 8 + grp) * 132 + ks * 8;
            uint32_t bh[2], bl[2];
            bh[0] = smem[SW_H + wB + qp];
            bh[1] = smem[SW_H + wB + 4 + qp];
            bl[0] = smem[SW_L + wB + qp];
            bl[1] = smem[SW_L + wB + 4 + qp];
            mma_bf16(acc[j], ah, bh);
            mma_bf16(acc[j], ah, bl);
            mma_bf16(acc[j], al, bh);
        }
    }

    // ---- Epilogue: + bias, store fp32 ----
    int row_a = node0 + m0 + grp;
    int row_b = row_a + 8;
    #pragma unroll
    for (int j = 0; j < 8; j++) {
        int col = n0 + j * 8 + qp * 2;
        float2 bv = *reinterpret_cast<const float2*>(bias + col);
        if (row_a < N_NODES) {
            float2 o = make_float2(acc[j][0] + bv.x, acc[j][1] + bv.y);
            *reinterpret_cast<float2*>(out + (size_t)row_a * D_OUT + col) = o;
        }
        if (row_b < N_NODES) {
            float2 o = make_float2(acc[j][2] + bv.x, acc[j][3] + bv.y);
            *reinterpret_cast<float2*>(out + (size_t)row_b * D_OUT + col) = o;
        }
    }
}

// ---------------------------------------------------------------------------
extern "C" void kernel_launch(void* const* d_in, const int* in_sizes, int n_in,
                              void* d_out, int out_size) {
    const float* vdata   = (const float*)d_in[0];
    const float* edata_a = (const float*)d_in[1];
    const float* edata_b = (const float*)d_in[2];
    const int*   conn_a  = (const int*)d_in[3];
    const int*   conn_b  = (const int*)d_in[4];
    const float* W       = (const float*)d_in[5];
    const float* bias    = (const float*)d_in[6];
    float*       out     = (float*)d_out;

    // 0) W split/transpose image
    prep_w_kernel<<<(D_IN * D_OUT + 255) / 256, 256>>>(W);

    // 1) init concat buffer
    {
        int total = N_NODES * 64;
        init_x_kernel<<<(total + 255) / 256, 256>>>(vdata);
    }
    // 2) scatter a and b (receivers = conn[1, :])
    {
        int total = N_EDGES * 16;
        int blocks = (total + 255) / 256;
        scatter_kernel<<<blocks, 256>>>(edata_a, conn_a + N_EDGES, 0);
        scatter_kernel<<<blocks, 256>>>(edata_b, conn_b + N_EDGES, 64);
    }
    // 3) HMMA GEMM + bias
    {
        size_t smem_bytes = SMEM_WORDS * sizeof(uint32_t);   // 202752
        cudaFuncSetAttribute(gemm_mma_kernel,
                             cudaFuncAttributeMaxDynamicSharedMemorySize,
                             (int)smem_bytes);
        int blocks = (N_NODES + 63) / 64;
        gemm_mma_kernel<<<blocks, 256, smem_bytes>>>(bias, out);
    }
}